// round 14
// baseline (speedup 1.0000x reference)
#include <cuda_runtime.h>
#include <cstdint>

#define BROWS 2048
#define NCOLS 16384
#define NTHREADS 512
#define NPK 8                   /* packed f32x2 per thread (16 elems of half-row) */
#define HALF (NCOLS / 2)        /* 8192 elems per CTA */
#define HROWBYTES (HALF * 4)    /* 32 KB per input half-row */
#define NSM 148
#define GRIDC (2 * NSM)         /* 296 CTAs = 148 clusters of 2 */
#define SHIFT 20.0f

// ---- packed f32x2 helpers ----
__device__ __forceinline__ uint64_t pk2(float lo, float hi) {
    uint64_t r; asm("mov.b64 %0,{%1,%2};" : "=l"(r) : "f"(lo), "f"(hi)); return r;
}
__device__ __forceinline__ void upk2(uint64_t v, float& lo, float& hi) {
    asm("mov.b64 {%0,%1},%2;" : "=f"(lo), "=f"(hi) : "l"(v));
}
__device__ __forceinline__ uint64_t mul2(uint64_t a, uint64_t b) {
    uint64_t r; asm("mul.rn.f32x2 %0,%1,%2;" : "=l"(r) : "l"(a), "l"(b)); return r;
}
__device__ __forceinline__ uint64_t add2(uint64_t a, uint64_t b) {
    uint64_t r; asm("add.rn.f32x2 %0,%1,%2;" : "=l"(r) : "l"(a), "l"(b)); return r;
}
__device__ __forceinline__ uint64_t fma2(uint64_t a, uint64_t b, uint64_t c) {
    uint64_t r; asm("fma.rn.f32x2 %0,%1,%2,%3;" : "=l"(r) : "l"(a), "l"(b), "l"(c)); return r;
}
__device__ __forceinline__ uint32_t smem_u32(const void* p) {
    uint32_t a; asm("{ .reg .u64 t; cvta.to.shared.u64 t, %1; cvt.u32.u64 %0, t; }" : "=r"(a) : "l"(p));
    return a;
}
__device__ __forceinline__ void bulk_g2s(uint32_t dst, const void* gsrc, uint32_t bytes, uint32_t mbar) {
    asm volatile("cp.async.bulk.shared::cta.global.mbarrier::complete_tx::bytes [%0], [%1], %2, [%3];"
                 :: "r"(dst), "l"(gsrc), "r"(bytes), "r"(mbar) : "memory");
}
__device__ __forceinline__ void mbar_init(uint32_t mbar, uint32_t cnt) {
    asm volatile("mbarrier.init.shared.b64 [%0], %1;" :: "r"(mbar), "r"(cnt) : "memory");
}
__device__ __forceinline__ void mbar_expect_tx(uint32_t mbar, uint32_t bytes) {
    asm volatile("mbarrier.arrive.expect_tx.shared.b64 _, [%0], %1;" :: "r"(mbar), "r"(bytes) : "memory");
}
// local (TMA) wait — cta-scope acquire
__device__ __forceinline__ void mbar_wait(uint32_t mbar, uint32_t parity) {
    asm volatile(
        "{\n\t.reg .pred P;\n\t"
        "WL_%=:\n\t"
        "mbarrier.try_wait.parity.acquire.cta.shared::cta.b64 P, [%0], %1, 0x989680;\n\t"
        "@P bra.uni WD_%=;\n\t"
        "bra.uni WL_%=;\n\t"
        "WD_%=:\n\t}"
        :: "r"(mbar), "r"(parity) : "memory");
}
// cluster-scope acquire wait (data written remotely by peer CTA)
__device__ __forceinline__ void mbar_wait_clu(uint32_t mbar, uint32_t parity) {
    asm volatile(
        "{\n\t.reg .pred P;\n\t"
        "WL_%=:\n\t"
        "mbarrier.try_wait.parity.acquire.cluster.shared::cta.b64 P, [%0], %1, 0x989680;\n\t"
        "@P bra.uni WD_%=;\n\t"
        "bra.uni WL_%=;\n\t"
        "WD_%=:\n\t}"
        :: "r"(mbar), "r"(parity) : "memory");
}
__device__ __forceinline__ uint32_t mapa_peer(uint32_t local_addr, uint32_t peer_rank) {
    uint32_t r;
    asm("mapa.shared::cluster.u32 %0, %1, %2;" : "=r"(r) : "r"(local_addr), "r"(peer_rank));
    return r;
}
__device__ __forceinline__ void st_peer_f2(uint32_t addr, float x, float y) {
    asm volatile("st.shared::cluster.v2.f32 [%0], {%1, %2};" :: "r"(addr), "f"(x), "f"(y) : "memory");
}
__device__ __forceinline__ void mbar_arrive_peer(uint32_t remote_mbar) {
    asm volatile("mbarrier.arrive.release.cluster.shared::cluster.b64 _, [%0];"
                 :: "r"(remote_mbar) : "memory");
}
#define CLUSTER_SYNC() do {                                         \
    asm volatile("barrier.cluster.arrive.aligned;" ::: "memory");   \
    asm volatile("barrier.cluster.wait.aligned;" ::: "memory");     \
} while (0)

extern __shared__ char dynbuf[];   // [2*HROWBYTES]: scores half | g half

// Consume one smem slot -> e2 packed regs + packed S/Q accumulators.
#define CONSUME_SLOT(slot)                                                    \
    do {                                                                      \
        int i4 = tid + (slot) * NTHREADS;                                     \
        float4 a = reinterpret_cast<const float4*>(bufS)[i4];                 \
        float4 b = reinterpret_cast<const float4*>(bufG)[i4];                 \
        float q0 = __expf(a.x + b.x - SHIFT);                                 \
        float q1 = __expf(a.y + b.y - SHIFT);                                 \
        float q2 = __expf(a.z + b.z - SHIFT);                                 \
        float q3 = __expf(a.w + b.w - SHIFT);                                 \
        uint64_t p0 = pk2(q0, q1), p1 = pk2(q2, q3);                          \
        e2[(slot) * 2]     = p0;                                              \
        e2[(slot) * 2 + 1] = p1;                                              \
        SnP = add2(SnP, p0); SnP = add2(SnP, p1);                             \
        QnP = fma2(p0, p0, QnP); QnP = fma2(p1, p1, QnP);                     \
    } while (0)

// One 2-iteration deflation group with CLUSTER-wide (S,Q) reduction.
// PARITY FIX (R13 hang): red_mbar gets exactly 1 arrive per group, so its
// phase flips EVERY group -> wait parity = rp & 1 (was (rp>>1)&1: deadlock).
// Mailbox WAR chain: my send@n+1 follows my read@n; peer's overwrite@n+2
// follows my arrive@n+1 — ping-pong slots (rp&1) are safe.
#define GROUP(DOACC)                                                          \
    do {                                                                      \
        float s1 = S, q1 = Q;                                                 \
        _Pragma("unroll")                                                     \
        for (int o = 16; o; o >>= 1) {                                        \
            s1 += __shfl_xor_sync(0xffffffffu, s1, o);                        \
            q1 += __shfl_xor_sync(0xffffffffu, q1, o);                        \
        }                                                                     \
        const int sl = rp & 1;                                                \
        float2* rb = red[sl];                                                 \
        if (l == 0) rb[w] = make_float2(s1, q1);                              \
        __syncthreads();                                                      \
        uint4 pv = *reinterpret_cast<const uint4*>(&rb[(l & 7) * 2]);         \
        float Sh = __uint_as_float(pv.x) + __uint_as_float(pv.z);             \
        float Qh = __uint_as_float(pv.y) + __uint_as_float(pv.w);             \
        _Pragma("unroll")                                                     \
        for (int o = 4; o; o >>= 1) {                                         \
            Sh += __shfl_xor_sync(0xffffffffu, Sh, o);                        \
            Qh += __shfl_xor_sync(0xffffffffu, Qh, o);                        \
        }                                                                     \
        if (tid == 0) {      /* send our half-sums to peer's mailbox */      \
            st_peer_f2(peer_mb + sl * 8, Sh, Qh);                             \
            mbar_arrive_peer(peer_red_mbar);                                  \
        }                                                                     \
        mbar_wait_clu(red_mbar_a, sl);                                        \
        float2 pm = mailbox[sl];                                              \
        rp++;                                                                 \
        const float Sb = Sh + pm.x;                                           \
        const float Qb = Qh + pm.y;                                           \
        const float i0 = __fdividef(c, Sb);                                   \
        const float S1 = fmaf(-i0, Qb, Sb);      /* Σ e(1-i0·e) exactly */    \
        const float i1 = __fdividef(c, S1);                                   \
        const uint64_t ninv0 = pk2(-i0, -i0);                                 \
        const uint64_t ninv1 = pk2(-i1, -i1);                                 \
        _Pragma("unroll")                                                     \
        for (int pq = 0; pq < NPK; pq++) {                                    \
            uint64_t ohn = mul2(e2[pq], ninv0);   /* -onehot */               \
            kn[pq] = add2(kn[pq], ohn);           /* kn -= onehot */          \
            e2[pq] = fma2(ohn, e2[pq], e2[pq]);   /* e *= 1-onehot */         \
        }                                                                     \
        uint64_t accS = 0ULL, accQ = 0ULL;                                    \
        _Pragma("unroll")                                                     \
        for (int pq = 0; pq < NPK; pq++) {                                    \
            uint64_t ohn = mul2(e2[pq], ninv1);                               \
            kn[pq] = add2(kn[pq], ohn);                                       \
            e2[pq] = fma2(ohn, e2[pq], e2[pq]);                               \
            if (DOACC) { accS = add2(accS, e2[pq]);                           \
                         accQ = fma2(e2[pq], e2[pq], accQ); }                 \
        }                                                                     \
        if (DOACC) {                                                          \
            float h0, h1;                                                     \
            upk2(accS, h0, h1); S = h0 + h1;                                  \
            upk2(accQ, h0, h1); Q = h0 + h1;                                  \
        }                                                                     \
    } while (0)

__global__ void __launch_bounds__(NTHREADS, 2) __cluster_dims__(2, 1, 1)
subset_op_kernel(const float* __restrict__ scores,
                 const float* __restrict__ gnoise,
                 float* __restrict__ out) {
    __shared__ alignas(16) float2 red[2][16];     // intra-CTA warp partials (ping-pong)
    __shared__ alignas(16) float2 mailbox[2];     // peer half-sums land here (ping-pong)
    __shared__ alignas(8) unsigned long long red_mbar_s, tma_mbar_s;

    const int tid = threadIdx.x;
    const int w = tid >> 5, l = tid & 31;
    uint32_t rank;
    asm("mov.u32 %0, %%cluster_ctarank;" : "=r"(rank));

    const uint32_t red_mbar_a = smem_u32(&red_mbar_s);
    const uint32_t tma_mbar_a = smem_u32(&tma_mbar_s);
    const uint32_t mb_local   = smem_u32(mailbox);
    const uint32_t bufa       = smem_u32(dynbuf);
    const uint32_t peer_mb       = mapa_peer(mb_local, rank ^ 1);
    const uint32_t peer_red_mbar = mapa_peer(red_mbar_a, rank ^ 1);
    const float* bufS = (const float*)dynbuf;
    const float* bufG = (const float*)(dynbuf + HROWBYTES);

    const float c = 0.999999f;   // inv = c/sum keeps onehot < 1 (replaces EPS clamp)

    if (tid == 0) {
        mbar_init(red_mbar_a, 1);   // 1 arrive per group (peer's elected thread)
        mbar_init(tma_mbar_a, 1);
    }
    __syncthreads();
    CLUSTER_SYNC();    // peer mbars initialized before any remote arrive

    const int cid = blockIdx.x >> 1;               // cluster id = row-group id
    const size_t colbase = (size_t)rank * HALF;    // this CTA's half of the row

    int row = cid;
    if (tid == 0) {    // prefetch first half-row
        mbar_expect_tx(tma_mbar_a, 2 * HROWBYTES);
        bulk_g2s(bufa,             scores + (size_t)row * NCOLS + colbase, HROWBYTES, tma_mbar_a);
        bulk_g2s(bufa + HROWBYTES, gnoise + (size_t)row * NCOLS + colbase, HROWBYTES, tma_mbar_a);
    }
    int tph = 0;       // TMA mbar parity
    int rp  = 0;       // reduction counter: slot = parity = rp & 1

    uint64_t e2[NPK], kn[NPK];
    float S, Q;

    for (; row < BROWS; row += NSM) {
        // ---- prologue: wait TMA, consume 4 slots into registers ----
        mbar_wait(tma_mbar_a, tph); tph ^= 1;
        {
            uint64_t SnP = 0ULL, QnP = 0ULL;
            CONSUME_SLOT(0); CONSUME_SLOT(1); CONSUME_SLOT(2); CONSUME_SLOT(3);
            float h0, h1;
            upk2(SnP, h0, h1); S = h0 + h1;
            upk2(QnP, h0, h1); Q = h0 + h1;
        }
#pragma unroll
        for (int i = 0; i < NPK; i++) kn[i] = 0ULL;
        __syncthreads();   // all threads done reading dynbuf

        // ---- prefetch next half-row under the compute window ----
        if ((row + NSM) < BROWS && tid == 0) {
            mbar_expect_tx(tma_mbar_a, 2 * HROWBYTES);
            bulk_g2s(bufa,             scores + (size_t)(row + NSM) * NCOLS + colbase, HROWBYTES, tma_mbar_a);
            bulk_g2s(bufa + HROWBYTES, gnoise + (size_t)(row + NSM) * NCOLS + colbase, HROWBYTES, tma_mbar_a);
        }

        // ---- 8 deflation groups (16 iterations) ----
        GROUP(1); GROUP(1); GROUP(1); GROUP(1);
        GROUP(1); GROUP(1); GROUP(1); GROUP(0);

        // ---- store khot = -kn for our half-row ----
        float* orow = out + (size_t)row * NCOLS + colbase;
#pragma unroll
        for (int i = 0; i < 4; i++) {
            float h0, h1, h2, h3;
            upk2(kn[2*i],   h0, h1);
            upk2(kn[2*i+1], h2, h3);
            float4 v;
            v.x = -h0; v.y = -h1; v.z = -h2; v.w = -h3;
            reinterpret_cast<float4*>(orow)[tid + i * NTHREADS] = v;
        }
    }

    // no CTA may exit while the peer could still remote-write our smem
    CLUSTER_SYNC();
}

extern "C" void kernel_launch(void* const* d_in, const int* in_sizes, int n_in,
                              void* d_out, int out_size) {
    const float* scores = (const float*)d_in[0];
    const float* g      = (const float*)d_in[1];
    float* out          = (float*)d_out;
    cudaFuncSetAttribute(subset_op_kernel,
                         cudaFuncAttributeMaxDynamicSharedMemorySize, 2 * HROWBYTES);
    subset_op_kernel<<<GRIDC, NTHREADS, 2 * HROWBYTES>>>(scores, g, out);
}

// round 15
// speedup vs baseline: 1.3890x; 1.3890x over previous
#include <cuda_runtime.h>
#include <cstdint>

#define BROWS 2048
#define NCOLS 16384
#define NTHREADS 512
#define NPK 16                  /* packed f32x2 per thread (32 elems) */
#define GRIDC 296               /* 2 CTAs per SM x 148 SMs, persistent */
#define SHIFT 20.0f

#define KN_OFF    0             /* 64 KB khot accumulator (negated) */
#define STAGE_OFF 65536         /* 48 KB TMA staging */
#define DYN_SMEM  (65536 + 49152)

// ---- packed f32x2 helpers ----
__device__ __forceinline__ uint64_t pk2(float lo, float hi) {
    uint64_t r; asm("mov.b64 %0,{%1,%2};" : "=l"(r) : "f"(lo), "f"(hi)); return r;
}
__device__ __forceinline__ void upk2(uint64_t v, float& lo, float& hi) {
    asm("mov.b64 {%0,%1},%2;" : "=f"(lo), "=f"(hi) : "l"(v));
}
__device__ __forceinline__ uint64_t mul2(uint64_t a, uint64_t b) {
    uint64_t r; asm("mul.rn.f32x2 %0,%1,%2;" : "=l"(r) : "l"(a), "l"(b)); return r;
}
__device__ __forceinline__ uint64_t add2(uint64_t a, uint64_t b) {
    uint64_t r; asm("add.rn.f32x2 %0,%1,%2;" : "=l"(r) : "l"(a), "l"(b)); return r;
}
__device__ __forceinline__ uint64_t fma2(uint64_t a, uint64_t b, uint64_t c) {
    uint64_t r; asm("fma.rn.f32x2 %0,%1,%2,%3;" : "=l"(r) : "l"(a), "l"(b), "l"(c)); return r;
}
__device__ __forceinline__ uint32_t smem_u32(const void* p) {
    uint32_t a; asm("{ .reg .u64 t; cvta.to.shared.u64 t, %1; cvt.u32.u64 %0, t; }" : "=r"(a) : "l"(p));
    return a;
}
__device__ __forceinline__ void bulk_g2s(uint32_t dst, const void* gsrc, uint32_t bytes, uint32_t mbar) {
    asm volatile("cp.async.bulk.shared::cta.global.mbarrier::complete_tx::bytes [%0], [%1], %2, [%3];"
                 :: "r"(dst), "l"(gsrc), "r"(bytes), "r"(mbar) : "memory");
}
__device__ __forceinline__ void mbar_init(uint32_t mbar, uint32_t cnt) {
    asm volatile("mbarrier.init.shared.b64 [%0], %1;" :: "r"(mbar), "r"(cnt) : "memory");
}
__device__ __forceinline__ void mbar_expect_tx(uint32_t mbar, uint32_t bytes) {
    asm volatile("mbarrier.arrive.expect_tx.shared.b64 _, [%0], %1;" :: "r"(mbar), "r"(bytes) : "memory");
}
__device__ __forceinline__ void mbar_wait(uint32_t mbar, uint32_t parity) {
    asm volatile(
        "{\n\t.reg .pred P;\n\t"
        "WL_%=:\n\t"
        "mbarrier.try_wait.parity.acquire.cta.shared::cta.b64 P, [%0], %1, 0x989680;\n\t"
        "@P bra.uni WD_%=;\n\t"
        "bra.uni WL_%=;\n\t"
        "WD_%=:\n\t}"
        :: "r"(mbar), "r"(parity) : "memory");
}

extern __shared__ char dynbuf[];

// Consume one 2048-elem unit: one float4 per array per thread -> 2 packed e2.
#define CONSUME_U(gu, soff, goff)                                             \
    do {                                                                      \
        float4 a = *reinterpret_cast<const float4*>(dynbuf + (soff) + tid * 16); \
        float4 b = *reinterpret_cast<const float4*>(dynbuf + (goff) + tid * 16); \
        float q0 = __expf(a.x + b.x - SHIFT);                                 \
        float q1 = __expf(a.y + b.y - SHIFT);                                 \
        float q2 = __expf(a.z + b.z - SHIFT);                                 \
        float q3 = __expf(a.w + b.w - SHIFT);                                 \
        uint64_t p0 = pk2(q0, q1), p1 = pk2(q2, q3);                          \
        e2[2 * (gu)]     = p0;                                                \
        e2[2 * (gu) + 1] = p1;                                                \
        SnP = add2(SnP, p0); SnP = add2(SnP, p1);                             \
        QnP = fma2(p0, p0, QnP); QnP = fma2(p1, p1, QnP);                     \
    } while (0)

// One 2-iteration deflation group; khot (negated) accumulates in SMEM.
// READKN=0 on the first group of a row (write-only: implicit kn zero-init).
#define GROUP(par, DOACC, READKN)                                             \
    do {                                                                      \
        float s1 = S, q1 = Q;                                                 \
        _Pragma("unroll")                                                     \
        for (int o = 16; o; o >>= 1) {                                        \
            s1 += __shfl_xor_sync(0xffffffffu, s1, o);                        \
            q1 += __shfl_xor_sync(0xffffffffu, q1, o);                        \
        }                                                                     \
        float2* rb = red[par];                                                \
        if (l == 0) rb[w] = make_float2(s1, q1);                              \
        __syncthreads();                                                      \
        float2 pp = rb[l & 15];                                               \
        float Sb = pp.x, Qb = pp.y;                                           \
        _Pragma("unroll")                                                     \
        for (int o = 8; o; o >>= 1) {                                         \
            Sb += __shfl_xor_sync(0xffffffffu, Sb, o);                        \
            Qb += __shfl_xor_sync(0xffffffffu, Qb, o);                        \
        }                                                                     \
        const float i0 = __fdividef(c, Sb);                                   \
        const float S1 = fmaf(-i0, Qb, Sb);      /* Σ e(1-i0·e) exactly */    \
        const float i1 = __fdividef(c, S1);                                   \
        const uint64_t ninv0 = pk2(-i0, -i0);                                 \
        const uint64_t ninv1 = pk2(-i1, -i1);                                 \
        uint64_t accS = 0ULL, accQ = 0ULL;                                    \
        _Pragma("unroll")                                                     \
        for (int s = 0; s < 8; s++) {                                         \
            uint64_t a0 = mul2(e2[2*s], ninv0);                               \
            e2[2*s]   = fma2(a0, e2[2*s], e2[2*s]);                           \
            uint64_t a1 = mul2(e2[2*s+1], ninv0);                             \
            e2[2*s+1] = fma2(a1, e2[2*s+1], e2[2*s+1]);                       \
            uint64_t b0 = mul2(e2[2*s], ninv1);                               \
            e2[2*s]   = fma2(b0, e2[2*s], e2[2*s]);                           \
            uint64_t b1 = mul2(e2[2*s+1], ninv1);                             \
            e2[2*s+1] = fma2(b1, e2[2*s+1], e2[2*s+1]);                       \
            uint64_t d0 = add2(a0, b0), d1 = add2(a1, b1);                    \
            ulonglong2* kp = reinterpret_cast<ulonglong2*>(                   \
                dynbuf + KN_OFF + s * 8192 + tid * 16);                       \
            if (READKN) {                                                     \
                ulonglong2 kv = *kp;                                          \
                kv.x = add2(kv.x, d0); kv.y = add2(kv.y, d1);                 \
                *kp = kv;                                                     \
            } else {                                                          \
                ulonglong2 kv; kv.x = d0; kv.y = d1; *kp = kv;                \
            }                                                                 \
            if (DOACC) {                                                      \
                accS = add2(accS, e2[2*s]); accS = add2(accS, e2[2*s+1]);     \
                accQ = fma2(e2[2*s], e2[2*s], accQ);                          \
                accQ = fma2(e2[2*s+1], e2[2*s+1], accQ);                      \
            }                                                                 \
        }                                                                     \
        if (DOACC) {                                                          \
            float h0, h1;                                                     \
            upk2(accS, h0, h1); S = h0 + h1;                                  \
            upk2(accQ, h0, h1); Q = h0 + h1;                                  \
        }                                                                     \
    } while (0)

__global__ void __launch_bounds__(NTHREADS, 2)
subset_op_kernel(const float* __restrict__ scores,
                 const float* __restrict__ gnoise,
                 float* __restrict__ out) {
    __shared__ alignas(16) float2 red[2][16];
    __shared__ alignas(8) unsigned long long mbA_s, mbB_s, mbC_s;

    const int tid = threadIdx.x;
    const int w = tid >> 5, l = tid & 31;
    const uint32_t mbA = smem_u32(&mbA_s);
    const uint32_t mbB = smem_u32(&mbB_s);
    const uint32_t mbC = smem_u32(&mbC_s);
    const uint32_t kn32    = smem_u32(dynbuf + KN_OFF);
    const uint32_t stage32 = smem_u32(dynbuf + STAGE_OFF);

    const float c = 0.999999f;   // inv = c/sum keeps onehot < 1 (replaces EPS clamp)

    if (tid == 0) { mbar_init(mbA, 1); mbar_init(mbB, 1); mbar_init(mbC, 1); }
    __syncthreads();

    int row = blockIdx.x;
    if (tid == 0) {   // prefetch wave A of first row: units 0-2 -> stage
        mbar_expect_tx(mbA, 49152);
        bulk_g2s(stage32,         scores + (size_t)row * NCOLS, 24576, mbA);
        bulk_g2s(stage32 + 24576, gnoise + (size_t)row * NCOLS, 24576, mbA);
    }
    int ph = 0;

    uint64_t e2[NPK];
    float S, Q;

    for (; row < BROWS; row += GRIDC) {
        const size_t rb = (size_t)row * NCOLS;

        // wave B: units 3-6 -> kn area (free: fresh, or post-store sync below)
        if (tid == 0) {
            mbar_expect_tx(mbB, 65536);
            bulk_g2s(kn32,         scores + rb + 6144, 32768, mbB);
            bulk_g2s(kn32 + 32768, gnoise + rb + 6144, 32768, mbB);
        }

        uint64_t SnP = 0ULL, QnP = 0ULL;

        // wave A: consume units 0-2 from stage
        mbar_wait(mbA, ph);
        CONSUME_U(0, STAGE_OFF,          STAGE_OFF + 24576);
        CONSUME_U(1, STAGE_OFF + 8192,   STAGE_OFF + 32768);
        CONSUME_U(2, STAGE_OFF + 16384,  STAGE_OFF + 40960);
        __syncthreads();   // all threads done reading wave-A bytes

        // wave C: unit 7 -> stage[0:16KB] (overwrites consumed wave-A region)
        if (tid == 0) {
            mbar_expect_tx(mbC, 16384);
            bulk_g2s(stage32,        scores + rb + 14336, 8192, mbC);
            bulk_g2s(stage32 + 8192, gnoise + rb + 14336, 8192, mbC);
        }

        // wave B: consume units 3-6 from kn area
        mbar_wait(mbB, ph);
        CONSUME_U(3, KN_OFF,          KN_OFF + 32768);
        CONSUME_U(4, KN_OFF + 8192,   KN_OFF + 40960);
        CONSUME_U(5, KN_OFF + 16384,  KN_OFF + 49152);
        CONSUME_U(6, KN_OFF + 24576,  KN_OFF + 57344);

        // wave C: consume unit 7
        mbar_wait(mbC, ph);
        CONSUME_U(7, STAGE_OFF, STAGE_OFF + 8192);

        { float h0, h1;
          upk2(SnP, h0, h1); S = h0 + h1;
          upk2(QnP, h0, h1); Q = h0 + h1; }

        // group 1: kn write-only (no zero-init pass needed).
        // Its internal __syncthreads also orders all consume-reads (waves B/C)
        // before kn STS and before the wave-A prefetch below.
        GROUP(0, 1, 0);

        if (tid == 0 && (row + GRIDC) < BROWS) {   // prefetch next row's wave A
            const size_t nb = (size_t)(row + GRIDC) * NCOLS;
            mbar_expect_tx(mbA, 49152);
            bulk_g2s(stage32,         scores + nb, 24576, mbA);
            bulk_g2s(stage32 + 24576, gnoise + nb, 24576, mbA);
        }

        // groups 2-8: kn read-modify-write
        GROUP(1, 1, 1); GROUP(0, 1, 1); GROUP(1, 1, 1);
        GROUP(0, 1, 1); GROUP(1, 1, 1); GROUP(0, 1, 1);
        GROUP(1, 0, 1);

        // ---- store khot = -kn (each thread reads only its own kn: no bar) ----
        float* orow = out + rb;
#pragma unroll
        for (int s = 0; s < 8; s++) {
            float4 kv = *reinterpret_cast<const float4*>(dynbuf + KN_OFF + s * 8192 + tid * 16);
            float4 v;
            v.x = -kv.x; v.y = -kv.y; v.z = -kv.z; v.w = -kv.w;
            *reinterpret_cast<float4*>(orow + s * 2048 + tid * 4) = v;
        }
        __syncthreads();   // all kn reads done before next row's wave B lands
        ph ^= 1;
    }
}

extern "C" void kernel_launch(void* const* d_in, const int* in_sizes, int n_in,
                              void* d_out, int out_size) {
    const float* scores = (const float*)d_in[0];
    const float* g      = (const float*)d_in[1];
    float* out          = (float*)d_out;
    cudaFuncSetAttribute(subset_op_kernel,
                         cudaFuncAttributeMaxDynamicSharedMemorySize, DYN_SMEM);
    subset_op_kernel<<<GRIDC, NTHREADS, DYN_SMEM>>>(scores, g, out);
}